// round 7
// baseline (speedup 1.0000x reference)
#include <cuda_runtime.h>

// YoloLoss: input/target (256, 25, 64, 64) f32 -> scalar f32.
// Row i = (b, y, x). Element (i, c) at base(b) + c*4096 + (i & 4095).
//
// Each thread handles 8 consecutive rows as TWO ADJACENT float4 groups per
// channel (interleaved loads, not serial chunks): per-iteration MLP doubles
// and grid = 512 = one full wave at 4 CTAs/SM.
// Tail: per-block fp32 partial -> i64 fixed point (x2^30, exact via double)
// -> atomicAdd(u64) => bit-deterministic; last block writes out + resets.

#define NROWS   (256 * 64 * 64)      // 1,048,576
#define THREADS 256
#define BLOCKS  (NROWS / 8 / THREADS)   // 512

#define COORD_W 5.0f
#define NOOBJ_W 0.5f
#define INV_BLOCKS (1.0f / 64.0f)
#define FP_SCALE 1073741824.0        // 2^30

__device__ unsigned long long g_sum;        // zero-init; reset by finisher
__device__ unsigned int       g_done_count; // zero-init; reset by finisher

// Box loss for one float4 group (4 rows). Writes masks, returns partial loss.
__device__ __forceinline__ float box_group(
    const float* __restrict__ pb, const float* __restrict__ tb, float* __restrict__ m)
{
    float P[5][4], T[5][4];
#pragma unroll
    for (int c = 0; c < 5; c++) {
        float4 pv = *reinterpret_cast<const float4*>(pb + c * 4096);
        float4 tv = *reinterpret_cast<const float4*>(tb + c * 4096);
        P[c][0] = pv.x; P[c][1] = pv.y; P[c][2] = pv.z; P[c][3] = pv.w;
        T[c][0] = tv.x; T[c][1] = tv.y; T[c][2] = tv.z; T[c][3] = tv.w;
    }

    float ls = 0.0f;
#pragma unroll
    for (int l = 0; l < 4; l++) {
        const float p0 = P[0][l], p1 = P[1][l], p2 = P[2][l], p3 = P[3][l], p4 = P[4][l];
        const float t0 = T[0][l], t1 = T[1][l], t2 = T[2][l], t3 = T[3][l], t4 = T[4][l];

        const float mm = (t4 > 0.0f) ? 1.0f : 0.0f;
        m[l] = mm;

        const float c1x = p0 * INV_BLOCKS, c1y = p1 * INV_BLOCKS;
        const float c2x = t0 * INV_BLOCKS, c2y = t1 * INV_BLOCKS;
        const float x1a = c1x - 0.5f * p2, x2a = c1x + 0.5f * p2;
        const float y1a = c1y - 0.5f * p3, y2a = c1y + 0.5f * p3;
        const float x1b = c2x - 0.5f * t2, x2b = c2x + 0.5f * t2;
        const float y1b = c2y - 0.5f * t3, y2b = c2y + 0.5f * t3;
        const float dx = fminf(x2a, x2b) - fmaxf(x1a, x1b);
        const float dy = fminf(y2a, y2b) - fmaxf(y1a, y1b);
        const float inter = dx * dy;
        const float uni   = p2 * p3 + t2 * t3 - inter;
        const bool  pos   = (dx > 0.0f) && (dy > 0.0f);
        const float iou   = pos ? (inter / uni) : 0.0f;

        const float sp2 = sqrtf(p2), sp3 = sqrtf(p3);
        const float st2 = sqrtf(t2), st3 = sqrtf(t3);

        const float dxy = (p0 - t0) * (p0 - t0) + (p1 - t1) * (p1 - t1);
        const float dwh = (sp2 - st2) * (sp2 - st2) + (sp3 - st3) * (sp3 - st3);
        const float dcf = (p4 - iou) * (p4 - iou);
        const float dnb = p4 * p4;

        ls += mm * (COORD_W * (dxy + dwh) + dcf)
            + NOOBJ_W * (1.0f - mm) * dnb;
    }
    return ls;
}

__global__ void __launch_bounds__(THREADS, 4) yolo_loss_fused(
    const float* __restrict__ inp, const float* __restrict__ tgt,
    float* __restrict__ out)
{
    const int gid = blockIdx.x * THREADS + threadIdx.x;
    const int i0  = gid << 3;                 // first of 8 rows
    const int b   = i0 >> 12;                 // / 4096  (8 | 4096: no straddle)
    const int off = i0 & 4095;
    const float* __restrict__ pb = inp + (size_t)b * (25 * 4096) + off;
    const float* __restrict__ tb = tgt + (size_t)b * (25 * 4096) + off;

    float mA[4], mB[4];
    float lsum = box_group(pb,     tb,     mA);
    lsum      += box_group(pb + 4, tb + 4, mB);

    // Class channels 5..24: 4 independent LDG.128 per iteration.
#pragma unroll
    for (int c = 5; c < 25; c++) {
        float4 pA = *reinterpret_cast<const float4*>(pb + c * 4096);
        float4 pB = *reinterpret_cast<const float4*>(pb + c * 4096 + 4);
        float4 tA = *reinterpret_cast<const float4*>(tb + c * 4096);
        float4 tB = *reinterpret_cast<const float4*>(tb + c * 4096 + 4);
        float a0 = pA.x - tA.x, a1 = pA.y - tA.y, a2 = pA.z - tA.z, a3 = pA.w - tA.w;
        float b0 = pB.x - tB.x, b1 = pB.y - tB.y, b2 = pB.z - tB.z, b3 = pB.w - tB.w;
        lsum += mA[0] * a0 * a0 + mA[1] * a1 * a1 + mA[2] * a2 * a2 + mA[3] * a3 * a3
              + mB[0] * b0 * b0 + mB[1] * b1 * b1 + mB[2] * b2 * b2 + mB[3] * b3 * b3;
    }

    // Warp reduce.
#pragma unroll
    for (int o = 16; o > 0; o >>= 1)
        lsum += __shfl_xor_sync(0xFFFFFFFFu, lsum, o);

    __shared__ float ws[THREADS / 32];
    const int lane = threadIdx.x & 31;
    const int warp = threadIdx.x >> 5;
    if (lane == 0) ws[warp] = lsum;
    __syncthreads();

    if (threadIdx.x == 0) {
        float v = 0.0f;
#pragma unroll
        for (int w = 0; w < THREADS / 32; w++) v += ws[w];

        long long q = __double2ll_rn((double)v * FP_SCALE);
        atomicAdd(&g_sum, (unsigned long long)q);   // order-independent
        __threadfence();
        unsigned int prev = atomicAdd(&g_done_count, 1u);
        if (prev == BLOCKS - 1) {
            unsigned long long total = atomicAdd(&g_sum, 0ULL);
            out[0] = (float)((double)(long long)total * (1.0 / FP_SCALE));
            g_done_count = 0;   // reset for next graph replay
            g_sum = 0ULL;
            __threadfence();
        }
    }
}

extern "C" void kernel_launch(void* const* d_in, const int* in_sizes, int n_in,
                              void* d_out, int out_size)
{
    const float* inp = (const float*)d_in[0];
    const float* tgt = (const float*)d_in[1];
    float* out = (float*)d_out;

    yolo_loss_fused<<<BLOCKS, THREADS>>>(inp, tgt, out);
}

// round 8
// speedup vs baseline: 1.0601x; 1.0601x over previous
#include <cuda_runtime.h>

// YoloLoss: input/target (256, 25, 64, 64) f32 -> scalar f32.
// Row i = (b, y, x). Element (i, c) at base(b) + c*4096 + (i & 4095).
//
// Each thread handles 2 consecutive rows (one float2 per channel): small
// register footprint (~45 live) -> __launch_bounds__(256,5) -> 5 CTAs/SM,
// 40 warps resident (62.5% occ) for deeper SM-level load queue.
// Tail: per-block fp32 partial -> i64 fixed point (x2^30, exact via double)
// -> atomicAdd(u64) => bit-deterministic; last block writes out + resets.

#define NROWS   (256 * 64 * 64)      // 1,048,576
#define THREADS 256
#define BLOCKS  (NROWS / 2 / THREADS)   // 2048

#define COORD_W 5.0f
#define NOOBJ_W 0.5f
#define INV_BLOCKS (1.0f / 64.0f)
#define FP_SCALE 1073741824.0        // 2^30

__device__ unsigned long long g_sum;        // zero-init; reset by finisher
__device__ unsigned int       g_done_count; // zero-init; reset by finisher

__global__ void __launch_bounds__(THREADS, 5) yolo_loss_fused(
    const float* __restrict__ inp, const float* __restrict__ tgt,
    float* __restrict__ out)
{
    const int gid = blockIdx.x * THREADS + threadIdx.x;
    const int i0  = gid << 1;                 // first of 2 rows
    const int b   = i0 >> 12;                 // / 4096  (2 | 4096: no straddle)
    const int off = i0 & 4095;
    const float* __restrict__ pb = inp + (size_t)b * (25 * 4096) + off;
    const float* __restrict__ tb = tgt + (size_t)b * (25 * 4096) + off;

    // Front-batched loads of the 5 box channels (10x LDG.64, 20 regs).
    float P[5][2], T[5][2];
#pragma unroll
    for (int c = 0; c < 5; c++) {
        float2 pv = *reinterpret_cast<const float2*>(pb + c * 4096);
        float2 tv = *reinterpret_cast<const float2*>(tb + c * 4096);
        P[c][0] = pv.x; P[c][1] = pv.y;
        T[c][0] = tv.x; T[c][1] = tv.y;
    }

    float m[2];
    float lsum = 0.0f;

#pragma unroll
    for (int l = 0; l < 2; l++) {
        const float p0 = P[0][l], p1 = P[1][l], p2 = P[2][l], p3 = P[3][l], p4 = P[4][l];
        const float t0 = T[0][l], t1 = T[1][l], t2 = T[2][l], t3 = T[3][l], t4 = T[4][l];

        const float mm = (t4 > 0.0f) ? 1.0f : 0.0f;
        m[l] = mm;

        const float c1x = p0 * INV_BLOCKS, c1y = p1 * INV_BLOCKS;
        const float c2x = t0 * INV_BLOCKS, c2y = t1 * INV_BLOCKS;
        const float x1a = c1x - 0.5f * p2, x2a = c1x + 0.5f * p2;
        const float y1a = c1y - 0.5f * p3, y2a = c1y + 0.5f * p3;
        const float x1b = c2x - 0.5f * t2, x2b = c2x + 0.5f * t2;
        const float y1b = c2y - 0.5f * t3, y2b = c2y + 0.5f * t3;
        const float dx = fminf(x2a, x2b) - fmaxf(x1a, x1b);
        const float dy = fminf(y2a, y2b) - fmaxf(y1a, y1b);
        const float inter = dx * dy;
        const float uni   = p2 * p3 + t2 * t3 - inter;
        const bool  pos   = (dx > 0.0f) && (dy > 0.0f);
        const float iou   = pos ? (inter / uni) : 0.0f;

        const float sp2 = sqrtf(p2), sp3 = sqrtf(p3);
        const float st2 = sqrtf(t2), st3 = sqrtf(t3);

        const float dxy = (p0 - t0) * (p0 - t0) + (p1 - t1) * (p1 - t1);
        const float dwh = (sp2 - st2) * (sp2 - st2) + (sp3 - st3) * (sp3 - st3);
        const float dcf = (p4 - iou) * (p4 - iou);
        const float dnb = p4 * p4;

        lsum += mm * (COORD_W * (dxy + dwh) + dcf)
              + NOOBJ_W * (1.0f - mm) * dnb;
    }

    // Class channels 5..24: streamed float2 loads.
#pragma unroll
    for (int c = 5; c < 25; c++) {
        float2 pv = *reinterpret_cast<const float2*>(pb + c * 4096);
        float2 tv = *reinterpret_cast<const float2*>(tb + c * 4096);
        float d0 = pv.x - tv.x, d1 = pv.y - tv.y;
        lsum += m[0] * d0 * d0 + m[1] * d1 * d1;
    }

    // Warp reduce.
#pragma unroll
    for (int o = 16; o > 0; o >>= 1)
        lsum += __shfl_xor_sync(0xFFFFFFFFu, lsum, o);

    __shared__ float ws[THREADS / 32];
    const int lane = threadIdx.x & 31;
    const int warp = threadIdx.x >> 5;
    if (lane == 0) ws[warp] = lsum;
    __syncthreads();

    if (threadIdx.x == 0) {
        float v = 0.0f;
#pragma unroll
        for (int w = 0; w < THREADS / 32; w++) v += ws[w];

        long long q = __double2ll_rn((double)v * FP_SCALE);
        atomicAdd(&g_sum, (unsigned long long)q);   // order-independent
        __threadfence();
        unsigned int prev = atomicAdd(&g_done_count, 1u);
        if (prev == BLOCKS - 1) {
            unsigned long long total = atomicAdd(&g_sum, 0ULL);
            out[0] = (float)((double)(long long)total * (1.0 / FP_SCALE));
            g_done_count = 0;   // reset for next graph replay
            g_sum = 0ULL;
            __threadfence();
        }
    }
}

extern "C" void kernel_launch(void* const* d_in, const int* in_sizes, int n_in,
                              void* d_out, int out_size)
{
    const float* inp = (const float*)d_in[0];
    const float* tgt = (const float*)d_in[1];
    float* out = (float*)d_out;

    yolo_loss_fused<<<BLOCKS, THREADS>>>(inp, tgt, out);
}

// round 9
// speedup vs baseline: 1.1755x; 1.1089x over previous
#include <cuda_runtime.h>

// YoloLoss: input/target (256, 25, 64, 64) f32 -> scalar f32.
// Row i = (b, y, x). Element (i, c) at base(b) + c*4096 + (i & 4095).
// Each thread handles 4 consecutive rows (one float4 per channel).
//
// R6 structure (best: 34.9us, DRAM 77.4%) + __ldcs streaming loads
// (evict-first: no L2 allocation churn for this zero-reuse 210MB stream).
// Tail: per-block fp32 partial -> i64 fixed point (x2^30, exact via double)
// -> atomicAdd(u64) => bit-deterministic; last block writes out + resets.

#define NROWS   (256 * 64 * 64)      // 1,048,576
#define GROUPS  (NROWS / 4)          // 262,144
#define THREADS 256
#define BLOCKS  (GROUPS / THREADS)   // 1024

#define COORD_W 5.0f
#define NOOBJ_W 0.5f
#define INV_BLOCKS (1.0f / 64.0f)
#define FP_SCALE 1073741824.0        // 2^30

__device__ unsigned long long g_sum;        // zero-init; reset by finisher
__device__ unsigned int       g_done_count; // zero-init; reset by finisher

__device__ __forceinline__ float4 ldcs4(const float* p) {
    return __ldcs(reinterpret_cast<const float4*>(p));
}

__global__ void __launch_bounds__(THREADS, 4) yolo_loss_fused(
    const float* __restrict__ inp, const float* __restrict__ tgt,
    float* __restrict__ out)
{
    const int gid = blockIdx.x * THREADS + threadIdx.x;
    const int i0  = gid << 2;                 // first of 4 rows
    const int b   = i0 >> 12;                 // / 4096
    const int off = i0 & 4095;
    const float* __restrict__ pb = inp + (size_t)b * (25 * 4096) + off;
    const float* __restrict__ tb = tgt + (size_t)b * (25 * 4096) + off;

    // Front-batched loads of the 5 box channels (10x LDG.128.CS).
    float P[5][4], T[5][4];
#pragma unroll
    for (int c = 0; c < 5; c++) {
        float4 pv = ldcs4(pb + c * 4096);
        float4 tv = ldcs4(tb + c * 4096);
        P[c][0] = pv.x; P[c][1] = pv.y; P[c][2] = pv.z; P[c][3] = pv.w;
        T[c][0] = tv.x; T[c][1] = tv.y; T[c][2] = tv.z; T[c][3] = tv.w;
    }

    float m[4];
    float lsum = 0.0f;

#pragma unroll
    for (int l = 0; l < 4; l++) {
        const float p0 = P[0][l], p1 = P[1][l], p2 = P[2][l], p3 = P[3][l], p4 = P[4][l];
        const float t0 = T[0][l], t1 = T[1][l], t2 = T[2][l], t3 = T[3][l], t4 = T[4][l];

        const float mm = (t4 > 0.0f) ? 1.0f : 0.0f;
        m[l] = mm;

        const float c1x = p0 * INV_BLOCKS, c1y = p1 * INV_BLOCKS;
        const float c2x = t0 * INV_BLOCKS, c2y = t1 * INV_BLOCKS;
        const float x1a = c1x - 0.5f * p2, x2a = c1x + 0.5f * p2;
        const float y1a = c1y - 0.5f * p3, y2a = c1y + 0.5f * p3;
        const float x1b = c2x - 0.5f * t2, x2b = c2x + 0.5f * t2;
        const float y1b = c2y - 0.5f * t3, y2b = c2y + 0.5f * t3;
        const float dx = fminf(x2a, x2b) - fmaxf(x1a, x1b);
        const float dy = fminf(y2a, y2b) - fmaxf(y1a, y1b);
        const float inter = dx * dy;
        const float uni   = p2 * p3 + t2 * t3 - inter;
        const bool  pos   = (dx > 0.0f) && (dy > 0.0f);
        const float iou   = pos ? (inter / uni) : 0.0f;

        const float sp2 = sqrtf(p2), sp3 = sqrtf(p3);
        const float st2 = sqrtf(t2), st3 = sqrtf(t3);

        const float dxy = (p0 - t0) * (p0 - t0) + (p1 - t1) * (p1 - t1);
        const float dwh = (sp2 - st2) * (sp2 - st2) + (sp3 - st3) * (sp3 - st3);
        const float dcf = (p4 - iou) * (p4 - iou);
        const float dnb = p4 * p4;

        lsum += mm * (COORD_W * (dxy + dwh) + dcf)
              + NOOBJ_W * (1.0f - mm) * dnb;
    }

    // Class channels 5..24: streamed LDG.128.CS loads.
#pragma unroll
    for (int c = 5; c < 25; c++) {
        float4 pv = ldcs4(pb + c * 4096);
        float4 tv = ldcs4(tb + c * 4096);
        float d0 = pv.x - tv.x, d1 = pv.y - tv.y, d2 = pv.z - tv.z, d3 = pv.w - tv.w;
        lsum += m[0] * d0 * d0 + m[1] * d1 * d1 + m[2] * d2 * d2 + m[3] * d3 * d3;
    }

    // Warp reduce.
#pragma unroll
    for (int o = 16; o > 0; o >>= 1)
        lsum += __shfl_xor_sync(0xFFFFFFFFu, lsum, o);

    __shared__ float ws[THREADS / 32];
    const int lane = threadIdx.x & 31;
    const int warp = threadIdx.x >> 5;
    if (lane == 0) ws[warp] = lsum;
    __syncthreads();

    if (threadIdx.x == 0) {
        float v = 0.0f;
#pragma unroll
        for (int w = 0; w < THREADS / 32; w++) v += ws[w];

        long long q = __double2ll_rn((double)v * FP_SCALE);
        atomicAdd(&g_sum, (unsigned long long)q);   // order-independent
        __threadfence();
        unsigned int prev = atomicAdd(&g_done_count, 1u);
        if (prev == BLOCKS - 1) {
            unsigned long long total = atomicAdd(&g_sum, 0ULL);
            out[0] = (float)((double)(long long)total * (1.0 / FP_SCALE));
            g_done_count = 0;   // reset for next graph replay
            g_sum = 0ULL;
            __threadfence();
        }
    }
}

extern "C" void kernel_launch(void* const* d_in, const int* in_sizes, int n_in,
                              void* d_out, int out_size)
{
    const float* inp = (const float*)d_in[0];
    const float* tgt = (const float*)d_in[1];
    float* out = (float*)d_out;

    yolo_loss_fused<<<BLOCKS, THREADS>>>(inp, tgt, out);
}